// round 1
// baseline (speedup 1.0000x reference)
#include <cuda_runtime.h>
#include <cuda_bf16.h>
#include <math.h>

// ---- static problem config (matches reference) ----
#define N_ATOMS 16384
#define NUM_BATCH 32
#define ATOMS_PER_BATCH 512   // N_ATOMS / NUM_BATCH
#define N_PAIRS 1048576

#define ALPHA_F       0.401f            // 4/10 + 0.001
#define K2FAC_F       1.5547167f        // 0.25 / ALPHA^2 = 0.25/0.160801
#define TWO_PI_F      6.283185307179586f
#define ONE_OVER_SQRTPI_F 0.5641895835477563f
#define EPS_F         1e-8f

// scratch (no allocations allowed)
__device__ float g_recip[NUM_BATCH];
__device__ float g_wnorm[NUM_BATCH];

// ------------------------------------------------------------------
// init: zero output accumulator + per-batch recip accumulators
// ------------------------------------------------------------------
__global__ void k_init(float* __restrict__ out) {
    int i = blockIdx.x * blockDim.x + threadIdx.x;
    if (i < N_ATOMS) out[i] = 0.0f;
    if (i < NUM_BATCH) g_recip[i] = 0.0f;
}

// ------------------------------------------------------------------
// wnorm: per-batch sum of (q^2 + eps). Atoms are batch-contiguous
// (batch_seg = repeat(arange(B), N/B)).
// ------------------------------------------------------------------
__global__ void k_wnorm(const float* __restrict__ Qa) {
    int b = blockIdx.x;
    __shared__ float s[256];
    float acc = 0.0f;
    for (int a = threadIdx.x; a < ATOMS_PER_BATCH; a += 256) {
        float q = Qa[b * ATOMS_PER_BATCH + a];
        acc += q * q + EPS_F;
    }
    s[threadIdx.x] = acc;
    __syncthreads();
    for (int st = 128; st > 0; st >>= 1) {
        if (threadIdx.x < st) s[threadIdx.x] += s[threadIdx.x + st];
        __syncthreads();
    }
    if (threadIdx.x == 0) g_wnorm[b] = s[0];
}

// ------------------------------------------------------------------
// real space: per-pair energy, segmented sum over sorted idx_i.
// Each thread owns a contiguous chunk of CHUNK pairs and run-length
// accumulates before touching global atomics.
// ------------------------------------------------------------------
#define CHUNK 16

__device__ __forceinline__ float switch_fn(float r) {
    float x = (r - 2.5f) * 0.2f;   // (r - ON)/(OFF - ON), ON=2.5, OFF=7.5
    if (x <= 0.0f) return 1.0f;
    if (x >= 1.0f) return 0.0f;
    float fp = expf(-1.0f / x);
    float fm = expf(-1.0f / (1.0f - x));
    return fm / (fp + fm);
}

__global__ void k_real(const float* __restrict__ Qa,
                       const float* __restrict__ rij,
                       const int*   __restrict__ idx_i,
                       const int*   __restrict__ idx_j,
                       float* __restrict__ out) {
    int chunk = blockIdx.x * blockDim.x + threadIdx.x;
    int base = chunk * CHUNK;
    if (base >= N_PAIRS) return;

    float acc = 0.0f;
    int cur = idx_i[base];
#pragma unroll
    for (int p = 0; p < CHUNK; p++) {
        int ip = base + p;
        int ii = idx_i[ip];
        int jj = idx_j[ip];
        float r = rij[ip];
        float fac = __ldg(&Qa[ii]) * __ldg(&Qa[jj]);
        float f = switch_fn(r);
        float damped = rsqrtf(r * r + 1.0f);
        float coul = 1.0f / r;
        float pw = fac * (f * damped + (1.0f - f) * coul) * erfcf(ALPHA_F * r);
        if (ii != cur) {
            atomicAdd(&out[cur], acc);
            acc = 0.0f;
            cur = ii;
        }
        acc += pw;
    }
    atomicAdd(&out[cur], acc);
}

// ------------------------------------------------------------------
// reciprocal space: grid = (ceil(K/8), NUM_BATCH), 256 threads (8 warps).
// Each block: stage the batch's 512 atoms (q, theta = 2*pi*R/L) in SMEM.
// Each warp handles one k-vector: lanes cover 16 atoms each, shuffle-
// reduce structure factor, fold qg*|S|^2 into a block-shared scalar,
// then one global atomic per block into g_recip[b].
// ------------------------------------------------------------------
__global__ void k_recip(const float* __restrict__ Qa,
                        const float* __restrict__ R,
                        const float* __restrict__ cell,
                        const float* __restrict__ kmul,
                        int K) {
    int b = blockIdx.y;
    __shared__ float sq[ATOMS_PER_BATCH];
    __shared__ float sx[ATOMS_PER_BATCH];
    __shared__ float sy[ATOMS_PER_BATCH];
    __shared__ float sz[ATOMS_PER_BATCH];
    __shared__ float sacc;

    float Lx = cell[b * 9 + 0];
    float Ly = cell[b * 9 + 4];
    float Lz = cell[b * 9 + 8];
    float ax = TWO_PI_F / Lx;
    float ay = TWO_PI_F / Ly;
    float az = TWO_PI_F / Lz;

    if (threadIdx.x == 0) sacc = 0.0f;
    for (int a = threadIdx.x; a < ATOMS_PER_BATCH; a += blockDim.x) {
        int n = b * ATOMS_PER_BATCH + a;
        sq[a] = Qa[n];
        sx[a] = R[n * 3 + 0] * ax;
        sy[a] = R[n * 3 + 1] * ay;
        sz[a] = R[n * 3 + 2] * az;
    }
    __syncthreads();

    int warp = threadIdx.x >> 5;
    int lane = threadIdx.x & 31;
    int kk = blockIdx.x * (blockDim.x >> 5) + warp;

    if (kk < K) {
        float mx = kmul[kk * 3 + 0];
        float my = kmul[kk * 3 + 1];
        float mz = kmul[kk * 3 + 2];
        float kx = mx * ax, ky = my * ay, kz = mz * az;
        float k2 = kx * kx + ky * ky + kz * kz;

        float cr = 0.0f, ci = 0.0f;
#pragma unroll 4
        for (int a = lane; a < ATOMS_PER_BATCH; a += 32) {
            float d = fmaf(mx, sx[a], fmaf(my, sy[a], mz * sz[a]));
            float s, c;
            sincosf(d, &s, &c);
            cr = fmaf(sq[a], c, cr);
            ci = fmaf(sq[a], s, ci);
        }
#pragma unroll
        for (int o = 16; o > 0; o >>= 1) {
            cr += __shfl_down_sync(0xFFFFFFFFu, cr, o);
            ci += __shfl_down_sync(0xFFFFFFFFu, ci, o);
        }
        if (lane == 0) {
            float qg = expf(-K2FAC_F * k2) / k2;
            atomicAdd(&sacc, qg * (cr * cr + ci * ci));
        }
    }
    __syncthreads();
    if (threadIdx.x == 0) atomicAdd(&g_recip[b], sacc);
}

// ------------------------------------------------------------------
// finalize: out[n] += w * e_recip_b[batch] - e_self
// ------------------------------------------------------------------
__global__ void k_final(const float* __restrict__ Qa,
                        const float* __restrict__ cell,
                        const int*   __restrict__ batch_seg,
                        float* __restrict__ out) {
    int n = blockIdx.x * blockDim.x + threadIdx.x;
    if (n >= N_ATOMS) return;
    int b = batch_seg[n];
    float Lx = cell[b * 9 + 0];
    float Ly = cell[b * 9 + 4];
    float Lz = cell[b * 9 + 8];
    float q = Qa[n];
    float q2 = q * q;
    float w = (q2 + EPS_F) / g_wnorm[b];
    float erec = w * (TWO_PI_F / (Lx * Ly * Lz)) * g_recip[b];
    out[n] += erec - ALPHA_F * ONE_OVER_SQRTPI_F * q2;
}

// ------------------------------------------------------------------
extern "C" void kernel_launch(void* const* d_in, const int* in_sizes, int n_in,
                              void* d_out, int out_size) {
    const float* Qa        = (const float*)d_in[0];
    const float* rij       = (const float*)d_in[1];
    const float* R         = (const float*)d_in[2];
    const float* cell      = (const float*)d_in[3];
    const float* kmul      = (const float*)d_in[4];
    const int*   idx_i     = (const int*)d_in[5];
    const int*   idx_j     = (const int*)d_in[6];
    const int*   batch_seg = (const int*)d_in[7];
    float* out = (float*)d_out;

    int K = in_sizes[4] / 3;

    k_init<<<(N_ATOMS + 255) / 256, 256>>>(out);
    k_wnorm<<<NUM_BATCH, 256>>>(Qa);

    int nchunks = N_PAIRS / CHUNK;
    k_real<<<(nchunks + 255) / 256, 256>>>(Qa, rij, idx_i, idx_j, out);

    dim3 rgrid((K + 7) / 8, NUM_BATCH);
    k_recip<<<rgrid, 256>>>(Qa, R, cell, kmul, K);

    k_final<<<(N_ATOMS + 255) / 256, 256>>>(Qa, cell, batch_seg, out);
}

// round 2
// speedup vs baseline: 1.7472x; 1.7472x over previous
#include <cuda_runtime.h>
#include <cuda_bf16.h>
#include <math.h>

// ---- static problem config (matches reference) ----
#define N_ATOMS 16384
#define NUM_BATCH 32
#define ATOMS_PER_BATCH 512   // N_ATOMS / NUM_BATCH
#define N_PAIRS 1048576

#define ALPHA_F       0.401f            // 4/10 + 0.001
#define K2FAC_F       1.5547167f        // 0.25 / ALPHA^2
#define TWO_PI_F      6.283185307179586f
#define ONE_OVER_SQRTPI_F 0.5641895835477563f
#define EPS_F         1e-8f

// scratch (no allocations allowed)
__device__ float g_recip[NUM_BATCH];

// ------------------------------------------------------------------
// init: zero output accumulator + per-batch recip accumulators
// ------------------------------------------------------------------
__global__ void k_init(float* __restrict__ out) {
    int i = blockIdx.x * blockDim.x + threadIdx.x;
    if (i < N_ATOMS) out[i] = 0.0f;
    if (i < NUM_BATCH) g_recip[i] = 0.0f;
}

// ------------------------------------------------------------------
// real space: per-pair energy, segmented sum over sorted idx_i.
// Each thread owns a contiguous chunk of CHUNK pairs and run-length
// accumulates before touching global atomics.
// ------------------------------------------------------------------
#define CHUNK 16

__device__ __forceinline__ float switch_fn(float r) {
    float x = (r - 2.5f) * 0.2f;   // (r - ON)/(OFF - ON), ON=2.5, OFF=7.5
    if (x <= 0.0f) return 1.0f;
    if (x >= 1.0f) return 0.0f;
    float fp = __expf(-1.0f / x);
    float fm = __expf(-1.0f / (1.0f - x));
    return fm / (fp + fm);
}

__global__ void k_real(const float* __restrict__ Qa,
                       const float* __restrict__ rij,
                       const int*   __restrict__ idx_i,
                       const int*   __restrict__ idx_j,
                       float* __restrict__ out) {
    int chunk = blockIdx.x * blockDim.x + threadIdx.x;
    int base = chunk * CHUNK;
    if (base >= N_PAIRS) return;

    float acc = 0.0f;
    int cur = idx_i[base];
#pragma unroll
    for (int p = 0; p < CHUNK; p++) {
        int ip = base + p;
        int ii = idx_i[ip];
        int jj = idx_j[ip];
        float r = rij[ip];
        float fac = __ldg(&Qa[ii]) * __ldg(&Qa[jj]);
        float f = switch_fn(r);
        float damped = rsqrtf(r * r + 1.0f);
        float coul = __frcp_rn(r);
        float pw = fac * (f * damped + (1.0f - f) * coul) * erfcf(ALPHA_F * r);
        if (ii != cur) {
            atomicAdd(&out[cur], acc);
            acc = 0.0f;
            cur = ii;
        }
        acc += pw;
    }
    atomicAdd(&out[cur], acc);
}

// ------------------------------------------------------------------
// reciprocal space: grid = (ceil(K/8), NUM_BATCH), 256 threads (8 warps).
// Stage the batch's 512 atoms (theta = 2*pi*R/L, q) packed as float4 in
// SMEM. Each warp handles one k-vector; lanes cover 16 atoms each with
// __sincosf (MUFU fast path), shuffle-reduce the structure factor, fold
// qg*|S|^2 into a block scalar, one global atomic per block.
// ------------------------------------------------------------------
__global__ void k_recip(const float* __restrict__ Qa,
                        const float* __restrict__ R,
                        const float* __restrict__ cell,
                        const float* __restrict__ kmul,
                        int K) {
    int b = blockIdx.y;
    __shared__ float4 s4[ATOMS_PER_BATCH];   // (theta_x, theta_y, theta_z, q)
    __shared__ float sacc;

    float Lx = cell[b * 9 + 0];
    float Ly = cell[b * 9 + 4];
    float Lz = cell[b * 9 + 8];
    float ax = TWO_PI_F / Lx;
    float ay = TWO_PI_F / Ly;
    float az = TWO_PI_F / Lz;

    if (threadIdx.x == 0) sacc = 0.0f;
    for (int a = threadIdx.x; a < ATOMS_PER_BATCH; a += blockDim.x) {
        int n = b * ATOMS_PER_BATCH + a;
        float4 v;
        v.x = R[n * 3 + 0] * ax;
        v.y = R[n * 3 + 1] * ay;
        v.z = R[n * 3 + 2] * az;
        v.w = Qa[n];
        s4[a] = v;
    }
    __syncthreads();

    int warp = threadIdx.x >> 5;
    int lane = threadIdx.x & 31;
    int kk = blockIdx.x * (blockDim.x >> 5) + warp;

    if (kk < K) {
        float mx = kmul[kk * 3 + 0];
        float my = kmul[kk * 3 + 1];
        float mz = kmul[kk * 3 + 2];
        float kx = mx * ax, ky = my * ay, kz = mz * az;
        float k2 = kx * kx + ky * ky + kz * kz;

        float cr = 0.0f, ci = 0.0f;
#pragma unroll 4
        for (int a = lane; a < ATOMS_PER_BATCH; a += 32) {
            float4 v = s4[a];
            float d = fmaf(mx, v.x, fmaf(my, v.y, mz * v.z));
            float s, c;
            __sincosf(d, &s, &c);
            cr = fmaf(v.w, c, cr);
            ci = fmaf(v.w, s, ci);
        }
#pragma unroll
        for (int o = 16; o > 0; o >>= 1) {
            cr += __shfl_down_sync(0xFFFFFFFFu, cr, o);
            ci += __shfl_down_sync(0xFFFFFFFFu, ci, o);
        }
        if (lane == 0) {
            float qg = __expf(-K2FAC_F * k2) / k2;
            atomicAdd(&sacc, qg * (cr * cr + ci * ci));
        }
    }
    __syncthreads();
    if (threadIdx.x == 0) atomicAdd(&g_recip[b], sacc);
}

// ------------------------------------------------------------------
// finalize (fused wnorm): one block per batch, 512 threads = 512 atoms.
// Block-reduce wnorm, then out[n] += w * e_recip_b - e_self.
// ------------------------------------------------------------------
__global__ void k_final(const float* __restrict__ Qa,
                        const float* __restrict__ cell,
                        float* __restrict__ out) {
    int b = blockIdx.x;
    int a = threadIdx.x;            // 0..511
    int n = b * ATOMS_PER_BATCH + a;
    __shared__ float s[512];

    float q = Qa[n];
    float q2 = q * q;
    float w = q2 + EPS_F;

    s[a] = w;
    __syncthreads();
    for (int st = 256; st > 0; st >>= 1) {
        if (a < st) s[a] += s[a + st];
        __syncthreads();
    }
    float wnorm = s[0];

    float Lx = cell[b * 9 + 0];
    float Ly = cell[b * 9 + 4];
    float Lz = cell[b * 9 + 8];
    float erec_b = (TWO_PI_F / (Lx * Ly * Lz)) * g_recip[b];
    out[n] += (w / wnorm) * erec_b - ALPHA_F * ONE_OVER_SQRTPI_F * q2;
}

// ------------------------------------------------------------------
extern "C" void kernel_launch(void* const* d_in, const int* in_sizes, int n_in,
                              void* d_out, int out_size) {
    const float* Qa        = (const float*)d_in[0];
    const float* rij       = (const float*)d_in[1];
    const float* R         = (const float*)d_in[2];
    const float* cell      = (const float*)d_in[3];
    const float* kmul      = (const float*)d_in[4];
    const int*   idx_i     = (const int*)d_in[5];
    const int*   idx_j     = (const int*)d_in[6];
    float* out = (float*)d_out;

    int K = in_sizes[4] / 3;

    k_init<<<(N_ATOMS + 255) / 256, 256>>>(out);

    int nchunks = N_PAIRS / CHUNK;
    k_real<<<(nchunks + 255) / 256, 256>>>(Qa, rij, idx_i, idx_j, out);

    dim3 rgrid((K + 7) / 8, NUM_BATCH);
    k_recip<<<rgrid, 256>>>(Qa, R, cell, kmul, K);

    k_final<<<NUM_BATCH, ATOMS_PER_BATCH>>>(Qa, cell, out);
}

// round 5
// speedup vs baseline: 2.1381x; 1.2237x over previous
#include <cuda_runtime.h>
#include <cuda_bf16.h>
#include <math.h>

// ---- static problem config (matches reference) ----
#define N_ATOMS 16384
#define NUM_BATCH 32
#define ATOMS_PER_BATCH 512
#define N_PAIRS 1048576

#define ALPHA_F       0.401f            // 4/10 + 0.001
#define K2FAC_F       1.5547167f        // 0.25 / ALPHA^2
#define TWO_PI_F      6.283185307179586f
#define ONE_OVER_SQRTPI_F 0.5641895835477563f
#define EPS_F         1e-8f
#define FULL 0xFFFFFFFFu

#define REAL_BLOCKS 128                 // 128 blocks * 8 warps * 1024 pairs = 1M
#define PAIRS_PER_WARP 1024
#define KHALF_MAX 1600

// scratch (no allocations allowed)
__device__ float  g_recip[NUM_BATCH];
__device__ float  g_wnorm[NUM_BATCH];
__device__ float4 g_theta[N_ATOMS];     // (2pi*Rx/Lx, 2pi*Ry/Ly, 2pi*Rz/Lz, q)
__device__ float4 g_khalf[KHALF_MAX];   // canonical half of kmul
__device__ int    g_kcount;

// ------------------------------------------------------------------
// prep: blocks 0..31  -> per-batch wnorm + theta table
//       block  32     -> compact canonical half of kmul (weight 2 implied)
//       blocks 33..48 -> zero out[] (+ block 33 zeros g_recip)
// ------------------------------------------------------------------
__global__ void k_prep(const float* __restrict__ Qa,
                       const float* __restrict__ R,
                       const float* __restrict__ cell,
                       const float* __restrict__ kmul,
                       int K,
                       float* __restrict__ out) {
    int bid = blockIdx.x;
    int tid = threadIdx.x;

    if (bid < NUM_BATCH) {
        int b = bid;
        float ax = TWO_PI_F / cell[b * 9 + 0];
        float ay = TWO_PI_F / cell[b * 9 + 4];
        float az = TWO_PI_F / cell[b * 9 + 8];
        __shared__ float sred[256];
        float acc = 0.0f;
        for (int a = tid; a < ATOMS_PER_BATCH; a += 256) {
            int n = b * ATOMS_PER_BATCH + a;
            float q = Qa[n];
            float4 v;
            v.x = R[n * 3 + 0] * ax;
            v.y = R[n * 3 + 1] * ay;
            v.z = R[n * 3 + 2] * az;
            v.w = q;
            g_theta[n] = v;
            acc += q * q + EPS_F;
        }
        sred[tid] = acc;
        __syncthreads();
        for (int st = 128; st > 0; st >>= 1) {
            if (tid < st) sred[tid] += sred[tid + st];
            __syncthreads();
        }
        if (tid == 0) g_wnorm[b] = sred[0];
    } else if (bid == NUM_BATCH) {
        if (tid == 0) g_kcount = 0;
        __syncthreads();
        for (int k = tid; k < K; k += 256) {
            float mx = kmul[k * 3 + 0];
            float my = kmul[k * 3 + 1];
            float mz = kmul[k * 3 + 2];
            bool canon = (mx > 0.5f) ||
                         (fabsf(mx) < 0.5f &&
                          (my > 0.5f || (fabsf(my) < 0.5f && mz > 0.5f)));
            if (canon) {
                int slot = atomicAdd(&g_kcount, 1);
                if (slot < KHALF_MAX) g_khalf[slot] = make_float4(mx, my, mz, 0.0f);
            }
        }
    } else {
        int base = (bid - NUM_BATCH - 1) * 1024 + tid;
#pragma unroll
        for (int i = 0; i < 4; i++) {
            int n = base + i * 256;
            if (n < N_ATOMS) out[n] = 0.0f;
        }
        if (bid == NUM_BATCH + 1 && tid < NUM_BATCH) g_recip[tid] = 0.0f;
    }
}

// ------------------------------------------------------------------
// fused main: blocks [0, REAL_BLOCKS)      -> real space
//             blocks [REAL_BLOCKS, +32*KB) -> reciprocal space
// ------------------------------------------------------------------
__global__ void __launch_bounds__(256) k_main(
        const float* __restrict__ Qa,
        const float* __restrict__ rij,
        const int*   __restrict__ idx_i,
        const int*   __restrict__ idx_j,
        const float* __restrict__ cell,
        float* __restrict__ out) {
    int bid = blockIdx.x;
    int warp = threadIdx.x >> 5;
    int lane = threadIdx.x & 31;

    if (bid < REAL_BLOCKS) {
        // ---------------- real space ----------------
        int gw = bid * 8 + warp;
        int base = gw * PAIRS_PER_WARP;
#pragma unroll 2
        for (int it = 0; it < PAIRS_PER_WARP / 32; it++) {
            int p = base + it * 32 + lane;          // coalesced
            int ii = idx_i[p];
            int jj = idx_j[p];
            float r = rij[p];
            float fac = __ldg(&Qa[ii]) * __ldg(&Qa[jj]);

            // C-inf switch, fast path
            float x = (r - 2.5f) * 0.2f;
            float f;
            if (x <= 0.0f)      f = 1.0f;
            else if (x >= 1.0f) f = 0.0f;
            else {
                float fp = __expf(-__frcp_rn(x));
                float fm = __expf(-__frcp_rn(1.0f - x));
                f = fm * __frcp_rn(fp + fm);
            }
            float damped = rsqrtf(fmaf(r, r, 1.0f));
            float coul = __frcp_rn(r);

            // erfc via Abramowitz-Stegun 7.1.26 (abs err <= 1.5e-7)
            float xa = ALPHA_F * r;
            float t = __frcp_rn(fmaf(0.3275911f, xa, 1.0f));
            float poly = t * fmaf(t, fmaf(t, fmaf(t, fmaf(t, 1.061405429f,
                                -1.453152027f), 1.421413741f),
                                -0.284496736f), 0.254829592f);
            float er = poly * __expf(-xa * xa);

            float pw = fac * (f * damped + (1.0f - f) * coul) * er;

            // warp segmented reduction over sorted ii
            int prev = __shfl_up_sync(FULL, ii, 1);
            bool head = (lane == 0) || (ii != prev);
            unsigned hm = __ballot_sync(FULL, head);
            unsigned below = hm & (0xFFFFFFFFu >> (31 - lane));
            int hp = 31 - __clz(below);
            float s = pw;
#pragma unroll
            for (int d = 1; d < 32; d <<= 1) {
                float v = __shfl_up_sync(FULL, s, d);
                if (lane >= hp + d) s += v;
            }
            bool lastv = (lane == 31) || ((hm >> (lane + 1)) & 1u);
            if (lastv) atomicAdd(&out[ii], s);
        }
    } else {
        // ---------------- reciprocal space ----------------
        int rb = bid - REAL_BLOCKS;
        int b = rb & (NUM_BATCH - 1);          // spread batches across SMs
        int kblk = rb >> 5;
        __shared__ float4 s4[ATOMS_PER_BATCH];
        __shared__ float sacc;

        if (threadIdx.x == 0) sacc = 0.0f;
        for (int a = threadIdx.x; a < ATOMS_PER_BATCH; a += 256)
            s4[a] = g_theta[b * ATOMS_PER_BATCH + a];
        __syncthreads();

        int kk = kblk * 8 + warp;
        if (kk < g_kcount) {
            float4 km = g_khalf[kk];
            float ax = TWO_PI_F / cell[b * 9 + 0];
            float ay = TWO_PI_F / cell[b * 9 + 4];
            float az = TWO_PI_F / cell[b * 9 + 8];
            float kx = km.x * ax, ky = km.y * ay, kz = km.z * az;
            float k2 = kx * kx + ky * ky + kz * kz;

            float cr = 0.0f, ci = 0.0f;
#pragma unroll 4
            for (int a = lane; a < ATOMS_PER_BATCH; a += 32) {
                float4 v = s4[a];
                float d = fmaf(km.x, v.x, fmaf(km.y, v.y, km.z * v.z));
                float s, c;
                __sincosf(d, &s, &c);
                cr = fmaf(v.w, c, cr);
                ci = fmaf(v.w, s, ci);
            }
#pragma unroll
            for (int o = 16; o > 0; o >>= 1) {
                cr += __shfl_down_sync(FULL, cr, o);
                ci += __shfl_down_sync(FULL, ci, o);
            }
            if (lane == 0) {
                float qg = __expf(-K2FAC_F * k2) * __frcp_rn(k2);
                atomicAdd(&sacc, 2.0f * qg * (cr * cr + ci * ci));  // +k and -k
            }
        }
        __syncthreads();
        if (threadIdx.x == 0 && sacc != 0.0f) atomicAdd(&g_recip[b], sacc);
    }
}

// ------------------------------------------------------------------
// finalize: pure elementwise (wnorm precomputed in prep)
// ------------------------------------------------------------------
__global__ void k_final(const float* __restrict__ Qa,
                        const float* __restrict__ cell,
                        float* __restrict__ out) {
    int n = blockIdx.x * 256 + threadIdx.x;
    if (n >= N_ATOMS) return;
    int b = n >> 9;            // ATOMS_PER_BATCH = 512
    float Lx = cell[b * 9 + 0];
    float Ly = cell[b * 9 + 4];
    float Lz = cell[b * 9 + 8];
    float q = Qa[n];
    float q2 = q * q;
    float w = (q2 + EPS_F) / g_wnorm[b];
    float erec = w * (TWO_PI_F / (Lx * Ly * Lz)) * g_recip[b];
    out[n] += erec - ALPHA_F * ONE_OVER_SQRTPI_F * q2;
}

// ------------------------------------------------------------------
extern "C" void kernel_launch(void* const* d_in, const int* in_sizes, int n_in,
                              void* d_out, int out_size) {
    const float* Qa    = (const float*)d_in[0];
    const float* rij   = (const float*)d_in[1];
    const float* R     = (const float*)d_in[2];
    const float* cell  = (const float*)d_in[3];
    const float* kmul  = (const float*)d_in[4];
    const int*   idx_i = (const int*)d_in[5];
    const int*   idx_j = (const int*)d_in[6];
    float* out = (float*)d_out;

    int K = in_sizes[4] / 3;
    int kh_max = K / 2 + 1;                  // canonical half upper bound
    int kblocks = (kh_max + 7) / 8;          // 8 warps = 8 k-vectors per block

    k_prep<<<NUM_BATCH + 1 + 16, 256>>>(Qa, R, cell, kmul, K, out);

    int main_grid = REAL_BLOCKS + kblocks * NUM_BATCH;
    k_main<<<main_grid, 256>>>(Qa, rij, idx_i, idx_j, cell, out);

    k_final<<<(N_ATOMS + 255) / 256, 256>>>(Qa, cell, out);
}